// round 11
// baseline (speedup 1.0000x reference)
#include <cuda_runtime.h>

#define S_ 512
#define L_ 256
#define H_ 768
#define P_ 8
#define K_ 8
#define H4_ 192             // float4 per full row
#define HH4_ 96             // float4 per half row
#define SEG_ 72             // per-role capacity (64 max + 8 round-up slack)
#define THREADS_ 96

// Forced-order 16B load: asm volatile pins issue order so ptxas cannot
// serialize the batch; 8 consecutive LDG.E.128 -> true MLP=8.
#define LDG4(V, PTR)                                                        \
    asm volatile("ld.global.nc.v4.f32 {%0,%1,%2,%3}, [%4];"                 \
                 : "=f"((V).x), "=f"((V).y), "=f"((V).z), "=f"((V).w)       \
                 : "l"(PTR))

__global__ __launch_bounds__(THREADS_)
void srl_pool_kernel(const float* __restrict__ emb,
                     const int* __restrict__ idxV,  const int* __restrict__ mV,
                     const int* __restrict__ idxA0, const int* __restrict__ mA0,
                     const int* __restrict__ idxA1, const int* __restrict__ mA1,
                     const int* __restrict__ pred,
                     float* __restrict__ out)
{
    const int s     = blockIdx.x;
    const int hhalf = blockIdx.y;          // which 384-float half of H
    const int tid   = threadIdx.x;         // 0..95

    __shared__ int   s_idx[3][SEG_];
    __shared__ float s_w[3][SEG_];
    __shared__ int   s_n[3];

    // Pre-zero lists (padded slots: idx=0, w=0 -> harmless L1-hit loads).
    #pragma unroll
    for (int j = tid; j < 3 * SEG_; j += THREADS_) {
        s_idx[j / SEG_][j % SEG_] = 0;
        s_w[j / SEG_][j % SEG_]   = 0.0f;
    }
    if (tid < 3) s_n[tid] = 0;
    __syncthreads();

    // ---------- Phase 1: 24 lanes, one per (role, p); vectorized loads ----------
    if (tid < 3 * P_) {
        const int role = tid >> 3;
        const int p    = tid & 7;
        const int* __restrict__ idx =
            (role == 0) ? idxV : (role == 1) ? idxA0 : idxA1;
        const int* __restrict__ msk =
            (role == 0) ? mV : (role == 1) ? mA0 : mA1;

        const int base = (s * P_ + p) * K_;
        int4 iv0 = *reinterpret_cast<const int4*>(idx + base);
        int4 iv1 = *reinterpret_cast<const int4*>(idx + base + 4);
        int4 mv0 = *reinterpret_cast<const int4*>(msk + base);
        int4 mv1 = *reinterpret_cast<const int4*>(msk + base + 4);
        int4 pv0 = *reinterpret_cast<const int4*>(pred + s * P_);
        int4 pv1 = *reinterpret_cast<const int4*>(pred + s * P_ + 4);

        int li[K_] = { iv0.x, iv0.y, iv0.z, iv0.w, iv1.x, iv1.y, iv1.z, iv1.w };
        int lm[K_] = { mv0.x, mv0.y, mv0.z, mv0.w, mv1.x, mv1.y, mv1.z, mv1.w };

        int lv[K_];
        int cnt = 0;
        #pragma unroll
        for (int k = 0; k < K_; k++) {
            int v = (lm[k] != 0) & (li[k] < L_) & (li[k] >= 0);
            li[k] = min(max(li[k], 0), L_ - 1);
            lv[k] = v;
            cnt  += v;
        }

        int pown  = (p < 4) ? ((const int*)&pv0)[p] : ((const int*)&pv1)[p - 4];
        int npred = (pv0.x != 0) + (pv0.y != 0) + (pv0.z != 0) + (pv0.w != 0)
                  + (pv1.x != 0) + (pv1.y != 0) + (pv1.z != 0) + (pv1.w != 0);

        float w = 0.0f;
        if (pown != 0 && cnt > 0 && npred > 0)
            w = 1.0f / ((float)cnt * (float)npred);

        if (w != 0.0f) {
            int pos = atomicAdd(&s_n[role], cnt);
            #pragma unroll
            for (int k = 0; k < K_; k++) {
                if (lv[k]) {
                    s_idx[role][pos] = li[k];
                    s_w[role][pos]   = w;
                    pos++;
                }
            }
        }
    }
    __syncthreads();

    // ---------- Phase 2: forced MLP=8 weighted row-sum over this H-half ----------
    const float4* __restrict__ embc =
        reinterpret_cast<const float4*>(emb) + (size_t)s * L_ * H4_ + hhalf * HH4_ + tid;

    float4 a0 = make_float4(0.f, 0.f, 0.f, 0.f);
    float4 a1 = a0, a2 = a0;

    // Round counts up to multiple of 8 so every batch is full (pads: w=0, row=0).
    const int n0 = (s_n[0] + 7) & ~7;
    const int n1 = (s_n[1] + 7) & ~7;
    const int n2 = (s_n[2] + 7) & ~7;

    #define AXPY8(ACC, R, NR)                                                   \
    for (int j = 0; j < (NR); j += 8) {                                         \
        const float4* p0 = embc + s_idx[R][j+0] * H4_;                          \
        const float4* p1 = embc + s_idx[R][j+1] * H4_;                          \
        const float4* p2 = embc + s_idx[R][j+2] * H4_;                          \
        const float4* p3 = embc + s_idx[R][j+3] * H4_;                          \
        const float4* p4 = embc + s_idx[R][j+4] * H4_;                          \
        const float4* p5 = embc + s_idx[R][j+5] * H4_;                          \
        const float4* p6 = embc + s_idx[R][j+6] * H4_;                          \
        const float4* p7 = embc + s_idx[R][j+7] * H4_;                          \
        float4 v0, v1, v2, v3, v4, v5, v6, v7;                                  \
        LDG4(v0, p0); LDG4(v1, p1); LDG4(v2, p2); LDG4(v3, p3);                 \
        LDG4(v4, p4); LDG4(v5, p5); LDG4(v6, p6); LDG4(v7, p7);                 \
        float w0 = s_w[R][j+0], w1 = s_w[R][j+1];                               \
        float w2 = s_w[R][j+2], w3 = s_w[R][j+3];                               \
        float w4 = s_w[R][j+4], w5 = s_w[R][j+5];                               \
        float w6 = s_w[R][j+6], w7 = s_w[R][j+7];                               \
        ACC.x += w0*v0.x; ACC.y += w0*v0.y; ACC.z += w0*v0.z; ACC.w += w0*v0.w; \
        ACC.x += w1*v1.x; ACC.y += w1*v1.y; ACC.z += w1*v1.z; ACC.w += w1*v1.w; \
        ACC.x += w2*v2.x; ACC.y += w2*v2.y; ACC.z += w2*v2.z; ACC.w += w2*v2.w; \
        ACC.x += w3*v3.x; ACC.y += w3*v3.y; ACC.z += w3*v3.z; ACC.w += w3*v3.w; \
        ACC.x += w4*v4.x; ACC.y += w4*v4.y; ACC.z += w4*v4.z; ACC.w += w4*v4.w; \
        ACC.x += w5*v5.x; ACC.y += w5*v5.y; ACC.z += w5*v5.z; ACC.w += w5*v5.w; \
        ACC.x += w6*v6.x; ACC.y += w6*v6.y; ACC.z += w6*v6.z; ACC.w += w6*v6.w; \
        ACC.x += w7*v7.x; ACC.y += w7*v7.y; ACC.z += w7*v7.z; ACC.w += w7*v7.w; \
    }

    AXPY8(a0, 0, n0)
    AXPY8(a1, 1, n1)
    AXPY8(a2, 2, n2)
    #undef AXPY8

    // Output: (e_V, e_A0, e_A1) role-major, each (S, H) f32.
    float4* __restrict__ out4 =
        reinterpret_cast<float4*>(out) + (size_t)s * H4_ + hhalf * HH4_ + tid;
    out4[(size_t)0 * S_ * H4_] = a0;
    out4[(size_t)1 * S_ * H4_] = a1;
    out4[(size_t)2 * S_ * H4_] = a2;
}

extern "C" void kernel_launch(void* const* d_in, const int* in_sizes, int n_in,
                              void* d_out, int out_size)
{
    const float* emb   = (const float*)d_in[0];
    const int*   idxV  = (const int*)d_in[1];
    const int*   mV    = (const int*)d_in[2];
    const int*   idxA0 = (const int*)d_in[3];
    const int*   mA0   = (const int*)d_in[4];
    const int*   idxA1 = (const int*)d_in[5];
    const int*   mA1   = (const int*)d_in[6];
    const int*   pred  = (const int*)d_in[7];
    float* out = (float*)d_out;

    dim3 grid(S_, 2);
    srl_pool_kernel<<<grid, THREADS_>>>(emb, idxV, mV, idxA0, mA0, idxA1, mA1, pred, out);
}

// round 12
// speedup vs baseline: 1.4138x; 1.4138x over previous
#include <cuda_runtime.h>

#define S_ 512
#define L_ 256
#define H_ 768
#define P_ 8
#define K_ 8
#define H4_ 192             // float4 per full row
#define HH4_ 96             // float4 per half row
#define SEG_ 72             // per-role capacity (64 max + 8 round-up slack)
#define THREADS_ 96

// Forced-order 16B load: asm volatile pins issue order so ptxas cannot
// serialize the batch; 8 consecutive LDG.E.128 -> true MLP=8.
#define LDG4(V, PTR)                                                        \
    asm volatile("ld.global.nc.v4.f32 {%0,%1,%2,%3}, [%4];"                 \
                 : "=f"((V).x), "=f"((V).y), "=f"((V).z), "=f"((V).w)       \
                 : "l"(PTR))

__global__ __launch_bounds__(THREADS_, 1)   // <- the fix: grant full reg budget
void srl_pool_kernel(const float* __restrict__ emb,
                     const int* __restrict__ idxV,  const int* __restrict__ mV,
                     const int* __restrict__ idxA0, const int* __restrict__ mA0,
                     const int* __restrict__ idxA1, const int* __restrict__ mA1,
                     const int* __restrict__ pred,
                     float* __restrict__ out)
{
    const int s     = blockIdx.x;
    const int hhalf = blockIdx.y;          // which 384-float half of H
    const int tid   = threadIdx.x;         // 0..95

    __shared__ int   s_idx[3][SEG_];
    __shared__ float s_w[3][SEG_];
    __shared__ int   s_n[3];

    // Pre-zero lists (padded slots: idx=0, w=0 -> harmless L1-hit loads).
    #pragma unroll
    for (int j = tid; j < 3 * SEG_; j += THREADS_) {
        s_idx[j / SEG_][j % SEG_] = 0;
        s_w[j / SEG_][j % SEG_]   = 0.0f;
    }
    if (tid < 3) s_n[tid] = 0;
    __syncthreads();

    // ---------- Phase 1: 24 lanes, one per (role, p); vectorized loads ----------
    if (tid < 3 * P_) {
        const int role = tid >> 3;
        const int p    = tid & 7;
        const int* __restrict__ idx =
            (role == 0) ? idxV : (role == 1) ? idxA0 : idxA1;
        const int* __restrict__ msk =
            (role == 0) ? mV : (role == 1) ? mA0 : mA1;

        const int base = (s * P_ + p) * K_;
        int4 iv0 = *reinterpret_cast<const int4*>(idx + base);
        int4 iv1 = *reinterpret_cast<const int4*>(idx + base + 4);
        int4 mv0 = *reinterpret_cast<const int4*>(msk + base);
        int4 mv1 = *reinterpret_cast<const int4*>(msk + base + 4);
        int4 pv0 = *reinterpret_cast<const int4*>(pred + s * P_);
        int4 pv1 = *reinterpret_cast<const int4*>(pred + s * P_ + 4);

        int li[K_] = { iv0.x, iv0.y, iv0.z, iv0.w, iv1.x, iv1.y, iv1.z, iv1.w };
        int lm[K_] = { mv0.x, mv0.y, mv0.z, mv0.w, mv1.x, mv1.y, mv1.z, mv1.w };

        int lv[K_];
        int cnt = 0;
        #pragma unroll
        for (int k = 0; k < K_; k++) {
            int v = (lm[k] != 0) & (li[k] < L_) & (li[k] >= 0);
            li[k] = min(max(li[k], 0), L_ - 1);
            lv[k] = v;
            cnt  += v;
        }

        int pown  = (p < 4) ? ((const int*)&pv0)[p] : ((const int*)&pv1)[p - 4];
        int npred = (pv0.x != 0) + (pv0.y != 0) + (pv0.z != 0) + (pv0.w != 0)
                  + (pv1.x != 0) + (pv1.y != 0) + (pv1.z != 0) + (pv1.w != 0);

        float w = 0.0f;
        if (pown != 0 && cnt > 0 && npred > 0)
            w = 1.0f / ((float)cnt * (float)npred);

        if (w != 0.0f) {
            int pos = atomicAdd(&s_n[role], cnt);
            #pragma unroll
            for (int k = 0; k < K_; k++) {
                if (lv[k]) {
                    s_idx[role][pos] = li[k];
                    s_w[role][pos]   = w;
                    pos++;
                }
            }
        }
    }
    __syncthreads();

    // ---------- Phase 2: true MLP=8 weighted row-sum over this H-half ----------
    const float4* __restrict__ embc =
        reinterpret_cast<const float4*>(emb) + (size_t)s * L_ * H4_ + hhalf * HH4_ + tid;

    float4 a0 = make_float4(0.f, 0.f, 0.f, 0.f);
    float4 a1 = a0, a2 = a0;

    // Round counts up to multiple of 8 so every batch is full (pads: w=0, row=0).
    const int n0 = (s_n[0] + 7) & ~7;
    const int n1 = (s_n[1] + 7) & ~7;
    const int n2 = (s_n[2] + 7) & ~7;

    #define AXPY8(ACC, R, NR)                                                   \
    for (int j = 0; j < (NR); j += 8) {                                         \
        const float4* p0 = embc + s_idx[R][j+0] * H4_;                          \
        const float4* p1 = embc + s_idx[R][j+1] * H4_;                          \
        const float4* p2 = embc + s_idx[R][j+2] * H4_;                          \
        const float4* p3 = embc + s_idx[R][j+3] * H4_;                          \
        const float4* p4 = embc + s_idx[R][j+4] * H4_;                          \
        const float4* p5 = embc + s_idx[R][j+5] * H4_;                          \
        const float4* p6 = embc + s_idx[R][j+6] * H4_;                          \
        const float4* p7 = embc + s_idx[R][j+7] * H4_;                          \
        float4 v0, v1, v2, v3, v4, v5, v6, v7;                                  \
        LDG4(v0, p0); LDG4(v1, p1); LDG4(v2, p2); LDG4(v3, p3);                 \
        LDG4(v4, p4); LDG4(v5, p5); LDG4(v6, p6); LDG4(v7, p7);                 \
        float w0 = s_w[R][j+0], w1 = s_w[R][j+1];                               \
        float w2 = s_w[R][j+2], w3 = s_w[R][j+3];                               \
        float w4 = s_w[R][j+4], w5 = s_w[R][j+5];                               \
        float w6 = s_w[R][j+6], w7 = s_w[R][j+7];                               \
        ACC.x += w0*v0.x; ACC.y += w0*v0.y; ACC.z += w0*v0.z; ACC.w += w0*v0.w; \
        ACC.x += w1*v1.x; ACC.y += w1*v1.y; ACC.z += w1*v1.z; ACC.w += w1*v1.w; \
        ACC.x += w2*v2.x; ACC.y += w2*v2.y; ACC.z += w2*v2.z; ACC.w += w2*v2.w; \
        ACC.x += w3*v3.x; ACC.y += w3*v3.y; ACC.z += w3*v3.z; ACC.w += w3*v3.w; \
        ACC.x += w4*v4.x; ACC.y += w4*v4.y; ACC.z += w4*v4.z; ACC.w += w4*v4.w; \
        ACC.x += w5*v5.x; ACC.y += w5*v5.y; ACC.z += w5*v5.z; ACC.w += w5*v5.w; \
        ACC.x += w6*v6.x; ACC.y += w6*v6.y; ACC.z += w6*v6.z; ACC.w += w6*v6.w; \
        ACC.x += w7*v7.x; ACC.y += w7*v7.y; ACC.z += w7*v7.z; ACC.w += w7*v7.w; \
    }

    AXPY8(a0, 0, n0)
    AXPY8(a1, 1, n1)
    AXPY8(a2, 2, n2)
    #undef AXPY8

    // Output: (e_V, e_A0, e_A1) role-major, each (S, H) f32.
    float4* __restrict__ out4 =
        reinterpret_cast<float4*>(out) + (size_t)s * H4_ + hhalf * HH4_ + tid;
    out4[(size_t)0 * S_ * H4_] = a0;
    out4[(size_t)1 * S_ * H4_] = a1;
    out4[(size_t)2 * S_ * H4_] = a2;
}

extern "C" void kernel_launch(void* const* d_in, const int* in_sizes, int n_in,
                              void* d_out, int out_size)
{
    const float* emb   = (const float*)d_in[0];
    const int*   idxV  = (const int*)d_in[1];
    const int*   mV    = (const int*)d_in[2];
    const int*   idxA0 = (const int*)d_in[3];
    const int*   mA0   = (const int*)d_in[4];
    const int*   idxA1 = (const int*)d_in[5];
    const int*   mA1   = (const int*)d_in[6];
    const int*   pred  = (const int*)d_in[7];
    float* out = (float*)d_out;

    dim3 grid(S_, 2);
    srl_pool_kernel<<<grid, THREADS_>>>(emb, idxV, mV, idxA0, mA0, idxA1, mA1, pred, out);
}

// round 13
// speedup vs baseline: 1.6118x; 1.1400x over previous
#include <cuda_runtime.h>

#define S_ 512
#define L_ 256
#define H_ 768
#define P_ 8
#define K_ 8
#define H4_ 192             // float4 per full row
#define HH4_ 96             // float4 per half row
#define SEG_ 72             // per-role capacity (64 max + 8 round-up slack)
#define THREADS_ 96

// Forced-order 16B load: asm volatile pins issue order so ptxas cannot
// serialize the batch; 8 consecutive LDG.E.128 -> true MLP=8.
#define LDG4(V, PTR)                                                        \
    asm volatile("ld.global.nc.v4.f32 {%0,%1,%2,%3}, [%4];"                 \
                 : "=f"((V).x), "=f"((V).y), "=f"((V).z), "=f"((V).w)       \
                 : "l"(PTR))

// 65536/(96*7) ~= 97 regs: fits MLP=8 without spill AND 7 CTAs/SM residency.
__global__ __launch_bounds__(THREADS_, 7)
void srl_pool_kernel(const float* __restrict__ emb,
                     const int* __restrict__ idxV,  const int* __restrict__ mV,
                     const int* __restrict__ idxA0, const int* __restrict__ mA0,
                     const int* __restrict__ idxA1, const int* __restrict__ mA1,
                     const int* __restrict__ pred,
                     float* __restrict__ out)
{
    const int s     = blockIdx.x;
    const int hhalf = blockIdx.y;          // which 384-float half of H
    const int tid   = threadIdx.x;         // 0..95

    __shared__ int   s_idx[3][SEG_];
    __shared__ float s_w[3][SEG_];
    __shared__ int   s_n[3];

    // Pre-zero lists (padded slots: idx=0, w=0 -> harmless L1-hit loads).
    #pragma unroll
    for (int j = tid; j < 3 * SEG_; j += THREADS_) {
        s_idx[j / SEG_][j % SEG_] = 0;
        s_w[j / SEG_][j % SEG_]   = 0.0f;
    }
    if (tid < 3) s_n[tid] = 0;
    __syncthreads();

    // ---------- Phase 1: 24 lanes, one per (role, p); vectorized loads ----------
    if (tid < 3 * P_) {
        const int role = tid >> 3;
        const int p    = tid & 7;
        const int* __restrict__ idx =
            (role == 0) ? idxV : (role == 1) ? idxA0 : idxA1;
        const int* __restrict__ msk =
            (role == 0) ? mV : (role == 1) ? mA0 : mA1;

        const int base = (s * P_ + p) * K_;
        int4 iv0 = *reinterpret_cast<const int4*>(idx + base);
        int4 iv1 = *reinterpret_cast<const int4*>(idx + base + 4);
        int4 mv0 = *reinterpret_cast<const int4*>(msk + base);
        int4 mv1 = *reinterpret_cast<const int4*>(msk + base + 4);
        int4 pv0 = *reinterpret_cast<const int4*>(pred + s * P_);
        int4 pv1 = *reinterpret_cast<const int4*>(pred + s * P_ + 4);

        int li[K_] = { iv0.x, iv0.y, iv0.z, iv0.w, iv1.x, iv1.y, iv1.z, iv1.w };
        int lm[K_] = { mv0.x, mv0.y, mv0.z, mv0.w, mv1.x, mv1.y, mv1.z, mv1.w };

        int lv[K_];
        int cnt = 0;
        #pragma unroll
        for (int k = 0; k < K_; k++) {
            int v = (lm[k] != 0) & (li[k] < L_) & (li[k] >= 0);
            li[k] = min(max(li[k], 0), L_ - 1);
            lv[k] = v;
            cnt  += v;
        }

        int pown  = (p < 4) ? ((const int*)&pv0)[p] : ((const int*)&pv1)[p - 4];
        int npred = (pv0.x != 0) + (pv0.y != 0) + (pv0.z != 0) + (pv0.w != 0)
                  + (pv1.x != 0) + (pv1.y != 0) + (pv1.z != 0) + (pv1.w != 0);

        float w = 0.0f;
        if (pown != 0 && cnt > 0 && npred > 0)
            w = 1.0f / ((float)cnt * (float)npred);

        if (w != 0.0f) {
            int pos = atomicAdd(&s_n[role], cnt);
            #pragma unroll
            for (int k = 0; k < K_; k++) {
                if (lv[k]) {
                    s_idx[role][pos] = li[k];
                    s_w[role][pos]   = w;
                    pos++;
                }
            }
        }
    }
    __syncthreads();

    // ---------- Phase 2: true MLP=8 weighted row-sum over this H-half ----------
    const float4* __restrict__ embc =
        reinterpret_cast<const float4*>(emb) + (size_t)s * L_ * H4_ + hhalf * HH4_ + tid;

    float4 a0 = make_float4(0.f, 0.f, 0.f, 0.f);
    float4 a1 = a0, a2 = a0;

    // Round counts up to multiple of 8 so every batch is full (pads: w=0, row=0).
    const int n0 = (s_n[0] + 7) & ~7;
    const int n1 = (s_n[1] + 7) & ~7;
    const int n2 = (s_n[2] + 7) & ~7;

    #define AXPY8(ACC, R, NR)                                                   \
    for (int j = 0; j < (NR); j += 8) {                                         \
        const float4* p0 = embc + s_idx[R][j+0] * H4_;                          \
        const float4* p1 = embc + s_idx[R][j+1] * H4_;                          \
        const float4* p2 = embc + s_idx[R][j+2] * H4_;                          \
        const float4* p3 = embc + s_idx[R][j+3] * H4_;                          \
        const float4* p4 = embc + s_idx[R][j+4] * H4_;                          \
        const float4* p5 = embc + s_idx[R][j+5] * H4_;                          \
        const float4* p6 = embc + s_idx[R][j+6] * H4_;                          \
        const float4* p7 = embc + s_idx[R][j+7] * H4_;                          \
        float4 v0, v1, v2, v3, v4, v5, v6, v7;                                  \
        LDG4(v0, p0); LDG4(v1, p1); LDG4(v2, p2); LDG4(v3, p3);                 \
        LDG4(v4, p4); LDG4(v5, p5); LDG4(v6, p6); LDG4(v7, p7);                 \
        float w0 = s_w[R][j+0], w1 = s_w[R][j+1];                               \
        float w2 = s_w[R][j+2], w3 = s_w[R][j+3];                               \
        float w4 = s_w[R][j+4], w5 = s_w[R][j+5];                               \
        float w6 = s_w[R][j+6], w7 = s_w[R][j+7];                               \
        ACC.x += w0*v0.x; ACC.y += w0*v0.y; ACC.z += w0*v0.z; ACC.w += w0*v0.w; \
        ACC.x += w1*v1.x; ACC.y += w1*v1.y; ACC.z += w1*v1.z; ACC.w += w1*v1.w; \
        ACC.x += w2*v2.x; ACC.y += w2*v2.y; ACC.z += w2*v2.z; ACC.w += w2*v2.w; \
        ACC.x += w3*v3.x; ACC.y += w3*v3.y; ACC.z += w3*v3.z; ACC.w += w3*v3.w; \
        ACC.x += w4*v4.x; ACC.y += w4*v4.y; ACC.z += w4*v4.z; ACC.w += w4*v4.w; \
        ACC.x += w5*v5.x; ACC.y += w5*v5.y; ACC.z += w5*v5.z; ACC.w += w5*v5.w; \
        ACC.x += w6*v6.x; ACC.y += w6*v6.y; ACC.z += w6*v6.z; ACC.w += w6*v6.w; \
        ACC.x += w7*v7.x; ACC.y += w7*v7.y; ACC.z += w7*v7.z; ACC.w += w7*v7.w; \
    }

    AXPY8(a0, 0, n0)
    AXPY8(a1, 1, n1)
    AXPY8(a2, 2, n2)
    #undef AXPY8

    // Output: (e_V, e_A0, e_A1) role-major, each (S, H) f32.
    float4* __restrict__ out4 =
        reinterpret_cast<float4*>(out) + (size_t)s * H4_ + hhalf * HH4_ + tid;
    out4[(size_t)0 * S_ * H4_] = a0;
    out4[(size_t)1 * S_ * H4_] = a1;
    out4[(size_t)2 * S_ * H4_] = a2;
}

extern "C" void kernel_launch(void* const* d_in, const int* in_sizes, int n_in,
                              void* d_out, int out_size)
{
    const float* emb   = (const float*)d_in[0];
    const int*   idxV  = (const int*)d_in[1];
    const int*   mV    = (const int*)d_in[2];
    const int*   idxA0 = (const int*)d_in[3];
    const int*   mA0   = (const int*)d_in[4];
    const int*   idxA1 = (const int*)d_in[5];
    const int*   mA1   = (const int*)d_in[6];
    const int*   pred  = (const int*)d_in[7];
    float* out = (float*)d_out;

    dim3 grid(S_, 2);
    srl_pool_kernel<<<grid, THREADS_>>>(emb, idxV, mV, idxA0, mA0, idxA1, mA1, pred, out);
}